// round 1
// baseline (speedup 1.0000x reference)
#include <cuda_runtime.h>
#include <math.h>

// Problem constants
#define BATCH   8
#define SEQ     2048
#define HID     256
#define NHEADS  8
#define HDIM    32
#define ROWS    (BATCH * SEQ)        // 16384

// Scratch (static device arrays — no allocation)
__device__ float g_q[BATCH * NHEADS * SEQ * HDIM];    // [b][h][s][d]
__device__ float g_k[BATCH * NHEADS * SEQ * HDIM];
__device__ float g_v[BATCH * NHEADS * SEQ * HDIM];
__device__ float g_ctx[ROWS * HID];                   // [b*s][h*HDIM+d]

// ---------------------------------------------------------------------------
// QKV GEMM: C[16384,768] = X[16384,256] @ Wqkv[256,768] + b
// Tiles: BM=64, BN=64, BK=32; 256 threads, 4x4 microtile.
// Epilogue scatters into g_q / g_k / g_v with [b][h][s][d] layout.
// ---------------------------------------------------------------------------
__global__ __launch_bounds__(256) void qkv_gemm(const float* __restrict__ X,
                                                const float* __restrict__ W,
                                                const float* __restrict__ bias) {
    __shared__ float Xs[64][36];   // [row][k], padded for STS128 alignment/banks
    __shared__ float Ws[32][68];   // [k][col], padded

    const int tx = threadIdx.x & 15;
    const int ty = threadIdx.x >> 4;
    const int m0 = blockIdx.y * 64;
    const int n0 = blockIdx.x * 64;

    float acc[4][4] = {};

    for (int kt = 0; kt < HID; kt += 32) {
        // Load X tile 64x32 (512 float4, 2 per thread)
        int e = threadIdx.x;
        #pragma unroll
        for (int p = 0; p < 2; p++, e += 256) {
            int row = e >> 3, c4 = e & 7;
            float4 v = *(const float4*)&X[(size_t)(m0 + row) * HID + kt + c4 * 4];
            *(float4*)&Xs[row][c4 * 4] = v;
        }
        // Load W tile 32x64
        e = threadIdx.x;
        #pragma unroll
        for (int p = 0; p < 2; p++, e += 256) {
            int row = e >> 4, c4 = e & 15;
            float4 v = *(const float4*)&W[(size_t)(kt + row) * 768 + n0 + c4 * 4];
            *(float4*)&Ws[row][c4 * 4] = v;
        }
        __syncthreads();

        #pragma unroll
        for (int k = 0; k < 32; k++) {
            float a0 = Xs[4 * ty + 0][k];
            float a1 = Xs[4 * ty + 1][k];
            float a2 = Xs[4 * ty + 2][k];
            float a3 = Xs[4 * ty + 3][k];
            float4 bv = *(const float4*)&Ws[k][4 * tx];
            acc[0][0] += a0 * bv.x; acc[0][1] += a0 * bv.y; acc[0][2] += a0 * bv.z; acc[0][3] += a0 * bv.w;
            acc[1][0] += a1 * bv.x; acc[1][1] += a1 * bv.y; acc[1][2] += a1 * bv.z; acc[1][3] += a1 * bv.w;
            acc[2][0] += a2 * bv.x; acc[2][1] += a2 * bv.y; acc[2][2] += a2 * bv.z; acc[2][3] += a2 * bv.w;
            acc[3][0] += a3 * bv.x; acc[3][1] += a3 * bv.y; acc[3][2] += a3 * bv.z; acc[3][3] += a3 * bv.w;
        }
        __syncthreads();
    }

    // Epilogue: scatter into q/k/v with [b][h][s][d] layout
    #pragma unroll
    for (int i = 0; i < 4; i++) {
        int r = m0 + 4 * ty + i;
        int b = r / SEQ;
        int s = r - b * SEQ;
        #pragma unroll
        for (int j = 0; j < 4; j++) {
            int cg = n0 + 4 * tx + j;       // 0..767
            int t  = cg >> 8;               // 0=q,1=k,2=v
            int rem = cg & 255;
            int nh = rem >> 5;
            int hd = rem & 31;
            float val = acc[i][j] + bias[cg];
            float* dst = (t == 0) ? g_q : (t == 1) ? g_k : g_v;
            dst[((size_t)(b * NHEADS + nh) * SEQ + s) * HDIM + hd] = val;
        }
    }
}

// ---------------------------------------------------------------------------
// Flash attention: one block per (b,h) x 64-query tile.
// Q,K stored K-major (transposed) in SMEM; P staged through SMEM for P@V.
// Online softmax, fp32 throughout. Writes ctx[b*s][h*32+d].
// ---------------------------------------------------------------------------
__global__ __launch_bounds__(256) void attn_kernel() {
    __shared__ float Qt[32][68];   // [k][qrow], pad 4 keeps float4 alignment
    __shared__ float Kt[32][68];   // [k][krow]
    __shared__ float Vs[64][36];   // [krow][d]
    __shared__ float Ps[64][64];   // [qrow][krow]

    const int tx = threadIdx.x & 15;
    const int ty = threadIdx.x >> 4;
    const int bh = blockIdx.y;              // 0..63
    const int b  = bh >> 3;
    const int h  = bh & 7;
    const int q0 = blockIdx.x * 64;
    const float scale = 0.1767766952966369f; // 1/sqrt(32)

    const size_t base = (size_t)(b * NHEADS + h) * SEQ * HDIM;
    const float* qp = g_q + base;
    const float* kp = g_k + base;
    const float* vp = g_v + base;

    // Load Q tile transposed, pre-scaled
    {
        int e = threadIdx.x;
        #pragma unroll
        for (int p = 0; p < 2; p++, e += 256) {
            int row = e >> 3, c4 = e & 7;
            float4 v = *(const float4*)&qp[(size_t)(q0 + row) * HDIM + c4 * 4];
            Qt[c4 * 4 + 0][row] = v.x * scale;
            Qt[c4 * 4 + 1][row] = v.y * scale;
            Qt[c4 * 4 + 2][row] = v.z * scale;
            Qt[c4 * 4 + 3][row] = v.w * scale;
        }
    }

    float m[4], l[4], o[4][2];
    #pragma unroll
    for (int i = 0; i < 4; i++) {
        m[i] = -INFINITY; l[i] = 0.f; o[i][0] = 0.f; o[i][1] = 0.f;
    }

    for (int kt = 0; kt < SEQ; kt += 64) {
        // Load K (transposed) and V tiles
        int e = threadIdx.x;
        #pragma unroll
        for (int p = 0; p < 2; p++, e += 256) {
            int row = e >> 3, c4 = e & 7;
            float4 kv = *(const float4*)&kp[(size_t)(kt + row) * HDIM + c4 * 4];
            Kt[c4 * 4 + 0][row] = kv.x;
            Kt[c4 * 4 + 1][row] = kv.y;
            Kt[c4 * 4 + 2][row] = kv.z;
            Kt[c4 * 4 + 3][row] = kv.w;
            float4 vv = *(const float4*)&vp[(size_t)(kt + row) * HDIM + c4 * 4];
            *(float4*)&Vs[row][c4 * 4] = vv;
        }
        __syncthreads();

        // S = (Q*scale) @ K^T   (64x64, 4x4 per thread)
        float s[4][4] = {};
        #pragma unroll
        for (int k = 0; k < 32; k++) {
            float4 qf = *(const float4*)&Qt[k][4 * ty];
            float4 kf = *(const float4*)&Kt[k][4 * tx];
            s[0][0] += qf.x * kf.x; s[0][1] += qf.x * kf.y; s[0][2] += qf.x * kf.z; s[0][3] += qf.x * kf.w;
            s[1][0] += qf.y * kf.x; s[1][1] += qf.y * kf.y; s[1][2] += qf.y * kf.z; s[1][3] += qf.y * kf.w;
            s[2][0] += qf.z * kf.x; s[2][1] += qf.z * kf.y; s[2][2] += qf.z * kf.z; s[2][3] += qf.z * kf.w;
            s[3][0] += qf.w * kf.x; s[3][1] += qf.w * kf.y; s[3][2] += qf.w * kf.z; s[3][3] += qf.w * kf.w;
        }

        // Online softmax per query row (rows 4*ty+i, stats across 16 tx lanes)
        #pragma unroll
        for (int i = 0; i < 4; i++) {
            float rm = fmaxf(fmaxf(s[i][0], s[i][1]), fmaxf(s[i][2], s[i][3]));
            #pragma unroll
            for (int off = 8; off >= 1; off >>= 1)
                rm = fmaxf(rm, __shfl_xor_sync(0xffffffffu, rm, off));
            float mn    = fmaxf(m[i], rm);
            float alpha = __expf(m[i] - mn);
            m[i] = mn;
            float p0 = __expf(s[i][0] - mn);
            float p1 = __expf(s[i][1] - mn);
            float p2 = __expf(s[i][2] - mn);
            float p3 = __expf(s[i][3] - mn);
            float rs = (p0 + p1) + (p2 + p3);
            #pragma unroll
            for (int off = 8; off >= 1; off >>= 1)
                rs += __shfl_xor_sync(0xffffffffu, rs, off);
            l[i] = l[i] * alpha + rs;
            o[i][0] *= alpha;
            o[i][1] *= alpha;
            float4 pv = make_float4(p0, p1, p2, p3);
            *(float4*)&Ps[4 * ty + i][4 * tx] = pv;
        }
        __syncthreads();

        // O += P @ V   (each thread: 4 rows x 2 cols of O)
        #pragma unroll
        for (int kv = 0; kv < 64; kv += 4) {
            float4 pf0 = *(const float4*)&Ps[4 * ty + 0][kv];
            float4 pf1 = *(const float4*)&Ps[4 * ty + 1][kv];
            float4 pf2 = *(const float4*)&Ps[4 * ty + 2][kv];
            float4 pf3 = *(const float4*)&Ps[4 * ty + 3][kv];
            {
                float2 vv = *(const float2*)&Vs[kv + 0][2 * tx];
                o[0][0] += pf0.x * vv.x; o[0][1] += pf0.x * vv.y;
                o[1][0] += pf1.x * vv.x; o[1][1] += pf1.x * vv.y;
                o[2][0] += pf2.x * vv.x; o[2][1] += pf2.x * vv.y;
                o[3][0] += pf3.x * vv.x; o[3][1] += pf3.x * vv.y;
            }
            {
                float2 vv = *(const float2*)&Vs[kv + 1][2 * tx];
                o[0][0] += pf0.y * vv.x; o[0][1] += pf0.y * vv.y;
                o[1][0] += pf1.y * vv.x; o[1][1] += pf1.y * vv.y;
                o[2][0] += pf2.y * vv.x; o[2][1] += pf2.y * vv.y;
                o[3][0] += pf3.y * vv.x; o[3][1] += pf3.y * vv.y;
            }
            {
                float2 vv = *(const float2*)&Vs[kv + 2][2 * tx];
                o[0][0] += pf0.z * vv.x; o[0][1] += pf0.z * vv.y;
                o[1][0] += pf1.z * vv.x; o[1][1] += pf1.z * vv.y;
                o[2][0] += pf2.z * vv.x; o[2][1] += pf2.z * vv.y;
                o[3][0] += pf3.z * vv.x; o[3][1] += pf3.z * vv.y;
            }
            {
                float2 vv = *(const float2*)&Vs[kv + 3][2 * tx];
                o[0][0] += pf0.w * vv.x; o[0][1] += pf0.w * vv.y;
                o[1][0] += pf1.w * vv.x; o[1][1] += pf1.w * vv.y;
                o[2][0] += pf2.w * vv.x; o[2][1] += pf2.w * vv.y;
                o[3][0] += pf3.w * vv.x; o[3][1] += pf3.w * vv.y;
            }
        }
        __syncthreads();
    }

    // Epilogue: ctx[b*s][h*32 + d] = O / l
    #pragma unroll
    for (int i = 0; i < 4; i++) {
        float inv = 1.0f / l[i];
        int sg = q0 + 4 * ty + i;
        float2 r = make_float2(o[i][0] * inv, o[i][1] * inv);
        *(float2*)&g_ctx[((size_t)b * SEQ + sg) * HID + h * HDIM + 2 * tx] = r;
    }
}

// ---------------------------------------------------------------------------
// Output projection: out[16384,256] = ctx @ Wout[256,256] + b_out
// ---------------------------------------------------------------------------
__global__ __launch_bounds__(256) void out_gemm(const float* __restrict__ W,
                                                const float* __restrict__ bias,
                                                float* __restrict__ out) {
    __shared__ float Xs[64][36];
    __shared__ float Ws[32][68];

    const int tx = threadIdx.x & 15;
    const int ty = threadIdx.x >> 4;
    const int m0 = blockIdx.y * 64;
    const int n0 = blockIdx.x * 64;

    float acc[4][4] = {};

    for (int kt = 0; kt < HID; kt += 32) {
        int e = threadIdx.x;
        #pragma unroll
        for (int p = 0; p < 2; p++, e += 256) {
            int row = e >> 3, c4 = e & 7;
            float4 v = *(const float4*)&g_ctx[(size_t)(m0 + row) * HID + kt + c4 * 4];
            *(float4*)&Xs[row][c4 * 4] = v;
        }
        e = threadIdx.x;
        #pragma unroll
        for (int p = 0; p < 2; p++, e += 256) {
            int row = e >> 4, c4 = e & 15;
            float4 v = *(const float4*)&W[(size_t)(kt + row) * HID + n0 + c4 * 4];
            *(float4*)&Ws[row][c4 * 4] = v;
        }
        __syncthreads();

        #pragma unroll
        for (int k = 0; k < 32; k++) {
            float a0 = Xs[4 * ty + 0][k];
            float a1 = Xs[4 * ty + 1][k];
            float a2 = Xs[4 * ty + 2][k];
            float a3 = Xs[4 * ty + 3][k];
            float4 bv = *(const float4*)&Ws[k][4 * tx];
            acc[0][0] += a0 * bv.x; acc[0][1] += a0 * bv.y; acc[0][2] += a0 * bv.z; acc[0][3] += a0 * bv.w;
            acc[1][0] += a1 * bv.x; acc[1][1] += a1 * bv.y; acc[1][2] += a1 * bv.z; acc[1][3] += a1 * bv.w;
            acc[2][0] += a2 * bv.x; acc[2][1] += a2 * bv.y; acc[2][2] += a2 * bv.z; acc[2][3] += a2 * bv.w;
            acc[3][0] += a3 * bv.x; acc[3][1] += a3 * bv.y; acc[3][2] += a3 * bv.z; acc[3][3] += a3 * bv.w;
        }
        __syncthreads();
    }

    #pragma unroll
    for (int i = 0; i < 4; i++) {
        int r = m0 + 4 * ty + i;
        #pragma unroll
        for (int j = 0; j < 4; j++) {
            int c = n0 + 4 * tx + j;
            out[(size_t)r * HID + c] = acc[i][j] + bias[c];
        }
    }
}

// ---------------------------------------------------------------------------
extern "C" void kernel_launch(void* const* d_in, const int* in_sizes, int n_in,
                              void* d_out, int out_size) {
    const float* x     = (const float*)d_in[0];
    const float* w_qkv = (const float*)d_in[1];
    const float* b_qkv = (const float*)d_in[2];
    const float* w_out = (const float*)d_in[3];
    const float* b_out = (const float*)d_in[4];
    float* out = (float*)d_out;

    qkv_gemm<<<dim3(12, ROWS / 64), 256>>>(x, w_qkv, b_qkv);
    attn_kernel<<<dim3(SEQ / 64, BATCH * NHEADS), 256>>>();
    out_gemm<<<dim3(HID / 64, ROWS / 64), 256>>>(w_out, b_out, out);
}